// round 13
// baseline (speedup 1.0000x reference)
#include <cuda_runtime.h>
#include <cstdint>

// ---------------------------------------------------------------------------
// Shapes:  X:(16,4096,512)  W1:(512,256) b1:(256)  W2:(256,64) b2:(64)
//          Wq/Wk/Wv/Wa:(64,64) ba:(64)  Wd:(64,512) bd:(512)
// PATCH=16 STRIDE=8 TOPK=8 EPS=1e-8 ; h=511 ; N=B*h=8176 ; M=B*L=65536
//
// Key identity: patches only consume Xe through 16-row means, and
// PATCH=16 = two aligned 8-row groups:
//   P[b,h] = (G[b,h] + G[b,h+1] + 16*b2) / 16
//   G[b,g] = (sum of 8 leaky(X@W1+b1) rows of group g) @ W2
// So enc1 emits group sums directly (g_Hs, 8 MB) and enc2/patch collapse
// into one tiny GEMM (k_p2).
// ---------------------------------------------------------------------------
#define MROWS 65536
#define DDIM  512
#define H1DIM 256
#define EDIM  64
#define NPAT  511
#define NROWS 8176
#define NGRP  8192      // 16 batches * 512 groups

__device__ float g_Hs[(size_t)NGRP * H1DIM];    //  8 MB  group-summed H1
__device__ float g_P [(size_t)NROWS * EDIM];    //  2 MB
__device__ float g_Z [(size_t)NROWS * EDIM];    //  2 MB

// ---------------------------------------------------------------------------
// K1: group-summed leaky(X @ W1 + b1).  M=65536 K=512 N=256 ; 128x128x16
// tiles, 8x8/thread.  Each thread's 8 accumulator rows are exactly one
// 8-row group -> epilogue reduces in registers, writes g_Hs (16 groups x
// 128 cols per block).
// grid (2, 512): bn on x so the two blocks sharing an A-tile are adjacent.
// ---------------------------------------------------------------------------
__global__ __launch_bounds__(256)
void k_enc1(const float* __restrict__ X, const float* __restrict__ W1,
            const float* __restrict__ bias1)
{
    __shared__ float As[2][16][132];
    __shared__ float Bs[2][16][128];
    const int bm = blockIdx.y * 128;
    const int bn = blockIdx.x * 128;
    const int tid = threadIdx.x;

    const int ar0 = tid >> 2;            // 0..63
    const int ar1 = ar0 + 64;
    const int ak  = (tid & 3) * 4;
    const int bk0 = tid >> 5;            // 0..7
    const int bk1 = bk0 + 8;
    const int bn4 = (tid & 31) * 4;

    const float* Ag = X + (size_t)bm * DDIM;

    float4 a0, a1, b0, b1;
    a0 = *(const float4*)(Ag + (size_t)ar0 * DDIM + ak);
    a1 = *(const float4*)(Ag + (size_t)ar1 * DDIM + ak);
    b0 = *(const float4*)(W1 + (size_t)bk0 * H1DIM + bn + bn4);
    b1 = *(const float4*)(W1 + (size_t)bk1 * H1DIM + bn + bn4);
    As[0][ak+0][ar0] = a0.x; As[0][ak+1][ar0] = a0.y; As[0][ak+2][ar0] = a0.z; As[0][ak+3][ar0] = a0.w;
    As[0][ak+0][ar1] = a1.x; As[0][ak+1][ar1] = a1.y; As[0][ak+2][ar1] = a1.z; As[0][ak+3][ar1] = a1.w;
    *(float4*)&Bs[0][bk0][bn4] = b0;
    *(float4*)&Bs[0][bk1][bn4] = b1;
    __syncthreads();

    const int tx = tid & 15, ty = tid >> 4;
    const int tm = ty * 8, tn = tx * 8;
    float acc[8][8] = {};

    #pragma unroll 1
    for (int kt = 0; kt < 32; ++kt) {
        const int cur = kt & 1;
        if (kt < 31) {
            const float* Ap = Ag + (kt + 1) * 16;
            a0 = *(const float4*)(Ap + (size_t)ar0 * DDIM + ak);
            a1 = *(const float4*)(Ap + (size_t)ar1 * DDIM + ak);
            const float* Bp = W1 + (size_t)(kt + 1) * 16 * H1DIM;
            b0 = *(const float4*)(Bp + (size_t)bk0 * H1DIM + bn + bn4);
            b1 = *(const float4*)(Bp + (size_t)bk1 * H1DIM + bn + bn4);
        }
        #pragma unroll
        for (int kk = 0; kk < 16; ++kk) {
            float4 av0 = *(float4*)&As[cur][kk][tm];
            float4 av1 = *(float4*)&As[cur][kk][tm + 4];
            float4 bv0 = *(float4*)&Bs[cur][kk][tn];
            float4 bv1 = *(float4*)&Bs[cur][kk][tn + 4];
            float aa[8] = {av0.x, av0.y, av0.z, av0.w, av1.x, av1.y, av1.z, av1.w};
            float bb[8] = {bv0.x, bv0.y, bv0.z, bv0.w, bv1.x, bv1.y, bv1.z, bv1.w};
            #pragma unroll
            for (int ii = 0; ii < 8; ++ii)
                #pragma unroll
                for (int jj = 0; jj < 8; ++jj)
                    acc[ii][jj] = fmaf(aa[ii], bb[jj], acc[ii][jj]);
        }
        if (kt < 31) {
            const int nx = cur ^ 1;
            As[nx][ak+0][ar0] = a0.x; As[nx][ak+1][ar0] = a0.y; As[nx][ak+2][ar0] = a0.z; As[nx][ak+3][ar0] = a0.w;
            As[nx][ak+0][ar1] = a1.x; As[nx][ak+1][ar1] = a1.y; As[nx][ak+2][ar1] = a1.z; As[nx][ak+3][ar1] = a1.w;
            *(float4*)&Bs[nx][bk0][bn4] = b0;
            *(float4*)&Bs[nx][bk1][bn4] = b1;
            __syncthreads();
        }
    }

    // epilogue: bias + leaky per element, then 8-row group sum in registers
    float bv[8];
    #pragma unroll
    for (int j = 0; j < 8; ++j) bv[j] = bias1[bn + tn + j];
    float gs[8] = {};
    #pragma unroll
    for (int ii = 0; ii < 8; ++ii) {
        #pragma unroll
        for (int jj = 0; jj < 8; ++jj) {
            float hx = acc[ii][jj] + bv[jj];
            gs[jj] += (hx >= 0.0f ? hx : 0.01f * hx);
        }
    }
    const int grp = (bm >> 3) + ty;          // global group 0..8191
    float* orow = g_Hs + (size_t)grp * H1DIM + bn + tn;
    *(float4*)(orow)     = make_float4(gs[0], gs[1], gs[2], gs[3]);
    *(float4*)(orow + 4) = make_float4(gs[4], gs[5], gs[6], gs[7]);
}

// ---------------------------------------------------------------------------
// K2: P[n] = ((Hs[b*512+h] + Hs[b*512+h+1]) @ W2 + 16*b2) / 16
// M=8176 K=256 N=64 ; 128x64x16 tiles, 8x4/thread; A gathered as pair sums.
// 64 blocks (8192 rows, last 16 guarded).
// ---------------------------------------------------------------------------
__global__ __launch_bounds__(256)
void k_p2(const float* __restrict__ W2, const float* __restrict__ bias2)
{
    __shared__ float As[2][16][132];
    __shared__ float Bs[2][16][64];
    const int bm = blockIdx.x * 128;
    const int tid = threadIdx.x;

    const int ar0 = tid >> 2;            // 0..63
    const int ar1 = ar0 + 64;
    const int ak  = (tid & 3) * 4;
    const int bk  = tid >> 4;            // 0..15
    const int bn4 = (tid & 15) * 4;

    // per-thread invariant row bases (clamped; extra rows never stored)
    int n0 = bm + ar0; if (n0 > NROWS - 1) n0 = NROWS - 1;
    int n1 = bm + ar1; if (n1 > NROWS - 1) n1 = NROWS - 1;
    const int b0i = n0 / NPAT, h0i = n0 - b0i * NPAT;
    const int b1i = n1 / NPAT, h1i = n1 - b1i * NPAT;
    const float* r0 = g_Hs + ((size_t)(b0i * 512 + h0i)) * H1DIM;
    const float* r1 = g_Hs + ((size_t)(b1i * 512 + h1i)) * H1DIM;

    float4 a0, a1, b0;
    {
        float4 p = *(const float4*)(r0 + ak);
        float4 q = *(const float4*)(r0 + H1DIM + ak);
        a0 = make_float4(p.x + q.x, p.y + q.y, p.z + q.z, p.w + q.w);
        p = *(const float4*)(r1 + ak);
        q = *(const float4*)(r1 + H1DIM + ak);
        a1 = make_float4(p.x + q.x, p.y + q.y, p.z + q.z, p.w + q.w);
    }
    b0 = *(const float4*)(W2 + (size_t)bk * EDIM + bn4);
    As[0][ak+0][ar0] = a0.x; As[0][ak+1][ar0] = a0.y; As[0][ak+2][ar0] = a0.z; As[0][ak+3][ar0] = a0.w;
    As[0][ak+0][ar1] = a1.x; As[0][ak+1][ar1] = a1.y; As[0][ak+2][ar1] = a1.z; As[0][ak+3][ar1] = a1.w;
    *(float4*)&Bs[0][bk][bn4] = b0;
    __syncthreads();

    const int tx = tid & 15, ty = tid >> 4;
    const int tm = ty * 8, tn = tx * 4;
    float acc[8][4] = {};

    #pragma unroll 1
    for (int kt = 0; kt < 16; ++kt) {
        const int cur = kt & 1;
        if (kt < 15) {
            const int ko = (kt + 1) * 16 + ak;
            float4 p = *(const float4*)(r0 + ko);
            float4 q = *(const float4*)(r0 + H1DIM + ko);
            a0 = make_float4(p.x + q.x, p.y + q.y, p.z + q.z, p.w + q.w);
            p = *(const float4*)(r1 + ko);
            q = *(const float4*)(r1 + H1DIM + ko);
            a1 = make_float4(p.x + q.x, p.y + q.y, p.z + q.z, p.w + q.w);
            b0 = *(const float4*)(W2 + (size_t)((kt + 1) * 16 + bk) * EDIM + bn4);
        }
        #pragma unroll
        for (int kk = 0; kk < 16; ++kk) {
            float4 av0 = *(float4*)&As[cur][kk][tm];
            float4 av1 = *(float4*)&As[cur][kk][tm + 4];
            float4 bv  = *(float4*)&Bs[cur][kk][tn];
            float aa[8] = {av0.x, av0.y, av0.z, av0.w, av1.x, av1.y, av1.z, av1.w};
            float bb[4] = {bv.x, bv.y, bv.z, bv.w};
            #pragma unroll
            for (int ii = 0; ii < 8; ++ii)
                #pragma unroll
                for (int jj = 0; jj < 4; ++jj)
                    acc[ii][jj] = fmaf(aa[ii], bb[jj], acc[ii][jj]);
        }
        if (kt < 15) {
            const int nx = cur ^ 1;
            As[nx][ak+0][ar0] = a0.x; As[nx][ak+1][ar0] = a0.y; As[nx][ak+2][ar0] = a0.z; As[nx][ak+3][ar0] = a0.w;
            As[nx][ak+0][ar1] = a1.x; As[nx][ak+1][ar1] = a1.y; As[nx][ak+2][ar1] = a1.z; As[nx][ak+3][ar1] = a1.w;
            *(float4*)&Bs[nx][bk][bn4] = b0;
            __syncthreads();
        }
    }

    float bv2[4];
    #pragma unroll
    for (int j = 0; j < 4; ++j) bv2[j] = bias2[tn + j];
    #pragma unroll
    for (int ii = 0; ii < 8; ++ii) {
        int n = bm + tm + ii;
        if (n < NROWS) {
            float4 o = make_float4(acc[ii][0] * 0.0625f + bv2[0],
                                   acc[ii][1] * 0.0625f + bv2[1],
                                   acc[ii][2] * 0.0625f + bv2[2],
                                   acc[ii][3] * 0.0625f + bv2[3]);
            *(float4*)(g_P + (size_t)n * EDIM + tn) = o;
        }
    }
}

// ---------------------------------------------------------------------------
// relu(tanh(m)) via odd deg-11 Taylor (|m|<=0.5), MUFU-free
// ---------------------------------------------------------------------------
__device__ __forceinline__ float arelu(float xi, float yi, float xj, float yj)
{
    float m  = fmaf(xi, yj, -(yi * xj));
    float m2 = m * m;
    float t;
    if (m2 > 0.25f) {
        t = tanhf(m);
    } else {
        float p = fmaf(m2, -8.863236e-3f, 2.1869488e-2f);
        p = fmaf(m2, p, -5.3968254e-2f);
        p = fmaf(m2, p,  1.3333334e-1f);
        p = fmaf(m2, p, -3.3333334e-1f);
        t = fmaf(m * m2, p, m);
    }
    return fmaxf(t, 0.0f);
}

// ---------------------------------------------------------------------------
// K4: attention + aggregation.  Single pass: patch index packed into the low
// 6 mantissa bits of the fp32 A-value; sorted top-8 chain gives masked sum
// and kept indices simultaneously.  (58.8us measured)
// ---------------------------------------------------------------------------
__global__ __launch_bounds__(512)
void k_attn(const float* __restrict__ Wq, const float* __restrict__ Wk,
            const float* __restrict__ Wv, const float* __restrict__ Wa,
            const float* __restrict__ ba)
{
    __shared__ float sWq[4096];
    __shared__ float sWk[4096];
    __shared__ float sp[512];
    __shared__ float sqn[512];
    __shared__ float skn[512];
    __shared__ float sv[512];
    __shared__ float sav[512];
    __shared__ float sred[32];

    const int tid = threadIdx.x;
    #pragma unroll
    for (int idx = tid; idx < 4096; idx += 512) {
        sWq[idx] = Wq[idx];
        sWk[idx] = Wk[idx];
    }
    const int r = tid >> 6;
    const int i = tid & 63;
    const int n = blockIdx.x * 8 + r;
    sp[tid] = g_P[(size_t)n * EDIM + i];
    __syncthreads();

    float q = 0.f, k = 0.f, v = 0.f;
    const float* prow = sp + r * 64;
    #pragma unroll 8
    for (int j = 0; j < 64; ++j) {
        float pj = prow[j];
        q = fmaf(pj, sWq[j * 64 + i], q);
        k = fmaf(pj, sWk[j * 64 + i], k);
        v = fmaf(pj, __ldg(Wv + j * 64 + i), v);
    }
    float q2 = q * q, k2 = k * k;
    #pragma unroll
    for (int o = 16; o > 0; o >>= 1) {
        q2 += __shfl_xor_sync(0xffffffffu, q2, o);
        k2 += __shfl_xor_sync(0xffffffffu, k2, o);
    }
    if ((i & 31) == 0) {
        int w = i >> 5;
        sred[r * 4 + w]     = q2;
        sred[r * 4 + 2 + w] = k2;
    }
    __syncthreads();
    const float invq = 1.0f / (sqrtf(sred[r * 4 + 0] + sred[r * 4 + 1]) + 1e-8f);
    const float invk = 1.0f / (sqrtf(sred[r * 4 + 2] + sred[r * 4 + 3]) + 1e-8f);
    sqn[tid] = q * invq;
    skn[tid] = k * invk;
    sv[tid]  = v;
    __syncthreads();

    const float xi = sqn[tid];
    const float yi = skn[tid];
    const float* xr = sqn + r * 64;
    const float* yr = skn + r * 64;
    const float* vr = sv  + r * 64;

    float t0=-1e30f,t1=-1e30f,t2=-1e30f,t3=-1e30f,
          t4=-1e30f,t5=-1e30f,t6=-1e30f,t7=-1e30f;
    #pragma unroll 8
    for (int j = 0; j < 64; ++j) {
        float a = arelu(xi, yi, xr[j], yr[j]);
        float y = __uint_as_float((__float_as_uint(a) & 0xFFFFFFC0u) | (uint32_t)j);
        float u;
        u = fminf(y, t0); t0 = fmaxf(y, t0); y = u;
        u = fminf(y, t1); t1 = fmaxf(y, t1); y = u;
        u = fminf(y, t2); t2 = fmaxf(y, t2); y = u;
        u = fminf(y, t3); t3 = fmaxf(y, t3); y = u;
        u = fminf(y, t4); t4 = fmaxf(y, t4); y = u;
        u = fminf(y, t5); t5 = fmaxf(y, t5); y = u;
        u = fminf(y, t6); t6 = fmaxf(y, t6); y = u;
        t7 = fmaxf(y, t7);
    }

    float S  = ((t0 + t1) + (t2 + t3)) + ((t4 + t5) + (t6 + t7));
    float av = 0.f;
    av = fmaf(t0, vr[__float_as_uint(t0) & 63u], av);
    av = fmaf(t1, vr[__float_as_uint(t1) & 63u], av);
    av = fmaf(t2, vr[__float_as_uint(t2) & 63u], av);
    av = fmaf(t3, vr[__float_as_uint(t3) & 63u], av);
    av = fmaf(t4, vr[__float_as_uint(t4) & 63u], av);
    av = fmaf(t5, vr[__float_as_uint(t5) & 63u], av);
    av = fmaf(t6, vr[__float_as_uint(t6) & 63u], av);
    av = fmaf(t7, vr[__float_as_uint(t7) & 63u], av);
    av = av / fmaxf(S, 1e-8f);
    sav[tid] = av;
    __syncthreads();

    float z = ba[i];
    const float* arow = sav + r * 64;
    #pragma unroll 8
    for (int j = 0; j < 64; ++j)
        z = fmaf(arow[j], __ldg(Wa + j * 64 + i), z);
    z = z >= 0.0f ? z : 0.01f * z;
    g_Z[(size_t)n * EDIM + i] = z;
}

// ---------------------------------------------------------------------------
// K5: fused scatter-average + decoder GEMM
// ---------------------------------------------------------------------------
__global__ __launch_bounds__(256)
void k_dec(const float* __restrict__ Wd, const float* __restrict__ bd,
           float* __restrict__ out)
{
    __shared__ float Azt[64][68];
    __shared__ float Bz[64][64];
    const int bm = blockIdx.x * 64;
    const int bn = blockIdx.y * 64;
    const int tid = threadIdx.x;

    {
        int k0 = tid >> 2;
        int c0 = (tid & 3) * 16;
        const float* src = Wd + (size_t)k0 * 512 + bn + c0;
        #pragma unroll
        for (int u = 0; u < 16; u += 4)
            *(float4*)&Bz[k0][c0 + u] = *(const float4*)(src + u);
    }
    {
        int rr = tid >> 2;
        int gr = bm + rr;
        int b  = gr >> 12;
        int l  = gr & 4095;
        int hb = l >> 3;
        int h0 = hb - 1;
        float s0 = (h0 >= 0)   ? 1.0f : 0.0f;
        float s1 = (hb <= 510) ? 1.0f : 0.0f;
        float inv = 1.0f / (s0 + s1);
        const float* z0 = g_Z + ((size_t)b * NPAT + (h0 >= 0   ? h0 : 0)) * 64;
        const float* z1 = g_Z + ((size_t)b * NPAT + (hb <= 510 ? hb : 0)) * 64;
        int kq = (tid & 3) * 16;
        #pragma unroll
        for (int u = 0; u < 16; u += 4) {
            float4 a0 = *(const float4*)(z0 + kq + u);
            float4 a1 = *(const float4*)(z1 + kq + u);
            Azt[kq + u + 0][rr] = fmaf(a0.x, s0, a1.x * s1) * inv;
            Azt[kq + u + 1][rr] = fmaf(a0.y, s0, a1.y * s1) * inv;
            Azt[kq + u + 2][rr] = fmaf(a0.z, s0, a1.z * s1) * inv;
            Azt[kq + u + 3][rr] = fmaf(a0.w, s0, a1.w * s1) * inv;
        }
    }
    __syncthreads();

    const int tx = tid & 15, ty = tid >> 4;
    const int tm = ty * 4, tn = tx * 4;
    float acc[4][4] = {};
    #pragma unroll
    for (int kk = 0; kk < 64; ++kk) {
        float4 a  = *(float4*)&Azt[kk][tm];
        float4 bq = *(float4*)&Bz[kk][tn];
        float aa[4] = {a.x, a.y, a.z, a.w};
        float bb[4] = {bq.x, bq.y, bq.z, bq.w};
        #pragma unroll
        for (int ii = 0; ii < 4; ++ii)
            #pragma unroll
            for (int jj = 0; jj < 4; ++jj)
                acc[ii][jj] = fmaf(aa[ii], bb[jj], acc[ii][jj]);
    }

    float4 bias = *(const float4*)(bd + bn + tn);
    float bb[4] = {bias.x, bias.y, bias.z, bias.w};
    #pragma unroll
    for (int ii = 0; ii < 4; ++ii) {
        float* orow = out + (size_t)(bm + tm + ii) * 512 + bn + tn;
        *(float4*)orow = make_float4(acc[ii][0] + bb[0], acc[ii][1] + bb[1],
                                     acc[ii][2] + bb[2], acc[ii][3] + bb[3]);
    }
}

// ---------------------------------------------------------------------------
extern "C" void kernel_launch(void* const* d_in, const int* in_sizes, int n_in,
                              void* d_out, int out_size)
{
    const float* X  = (const float*)d_in[0];
    const float* W1 = (const float*)d_in[1];
    const float* b1 = (const float*)d_in[2];
    const float* W2 = (const float*)d_in[3];
    const float* b2 = (const float*)d_in[4];
    const float* Wq = (const float*)d_in[5];
    const float* Wk = (const float*)d_in[6];
    const float* Wv = (const float*)d_in[7];
    const float* Wa = (const float*)d_in[8];
    const float* ba = (const float*)d_in[9];
    const float* Wd = (const float*)d_in[10];
    const float* bd = (const float*)d_in[11];
    float* out = (float*)d_out;

    k_enc1<<<dim3(2, 512), 256>>>(X, W1, b1);
    k_p2<<<64, 256>>>(W2, b2);
    k_attn<<<1022, 512>>>(Wq, Wk, Wv, Wa, ba);
    k_dec<<<dim3(1024, 8), 256>>>(Wd, bd, out);
}

// round 14
// speedup vs baseline: 1.0232x; 1.0232x over previous
#include <cuda_runtime.h>
#include <cstdint>

// ---------------------------------------------------------------------------
// Shapes:  X:(16,4096,512)  W1:(512,256) b1:(256)  W2:(256,64) b2:(64)
//          Wq/Wk/Wv/Wa:(64,64) ba:(64)  Wd:(64,512) bd:(512)
// PATCH=16 STRIDE=8 TOPK=8 EPS=1e-8 ; h=511 ; N=B*h=8176 ; M=B*L=65536
//
// Fusion identity: P[b,h] = ((Hs[b,h] + Hs[b,h+1]) @ W2 + 16*b2)/16 where
// Hs = 8-row group sums of leaky(X@W1+b1), emitted by enc1's epilogue.
// ---------------------------------------------------------------------------
#define MROWS 65536
#define DDIM  512
#define H1DIM 256
#define EDIM  64
#define NPAT  511
#define NROWS 8176
#define NGRP  8192      // 16 batches * 512 groups

__device__ float g_Hs[(size_t)NGRP * H1DIM];    //  8 MB  group-summed H1
__device__ float g_P [(size_t)NROWS * EDIM];    //  2 MB
__device__ float g_Z [(size_t)NROWS * EDIM];    //  2 MB

// ---------------------------------------------------------------------------
// K1: group-summed leaky(X @ W1 + b1).  M=65536 K=512 N=256 ; 128x128x16
// tiles, 8x8/thread; epilogue reduces each thread's 8 rows (one group).
// ---------------------------------------------------------------------------
__global__ __launch_bounds__(256)
void k_enc1(const float* __restrict__ X, const float* __restrict__ W1,
            const float* __restrict__ bias1)
{
    __shared__ float As[2][16][132];
    __shared__ float Bs[2][16][128];
    const int bm = blockIdx.y * 128;
    const int bn = blockIdx.x * 128;
    const int tid = threadIdx.x;

    const int ar0 = tid >> 2;            // 0..63
    const int ar1 = ar0 + 64;
    const int ak  = (tid & 3) * 4;
    const int bk0 = tid >> 5;            // 0..7
    const int bk1 = bk0 + 8;
    const int bn4 = (tid & 31) * 4;

    const float* Ag = X + (size_t)bm * DDIM;

    float4 a0, a1, b0, b1;
    a0 = *(const float4*)(Ag + (size_t)ar0 * DDIM + ak);
    a1 = *(const float4*)(Ag + (size_t)ar1 * DDIM + ak);
    b0 = *(const float4*)(W1 + (size_t)bk0 * H1DIM + bn + bn4);
    b1 = *(const float4*)(W1 + (size_t)bk1 * H1DIM + bn + bn4);
    As[0][ak+0][ar0] = a0.x; As[0][ak+1][ar0] = a0.y; As[0][ak+2][ar0] = a0.z; As[0][ak+3][ar0] = a0.w;
    As[0][ak+0][ar1] = a1.x; As[0][ak+1][ar1] = a1.y; As[0][ak+2][ar1] = a1.z; As[0][ak+3][ar1] = a1.w;
    *(float4*)&Bs[0][bk0][bn4] = b0;
    *(float4*)&Bs[0][bk1][bn4] = b1;
    __syncthreads();

    const int tx = tid & 15, ty = tid >> 4;
    const int tm = ty * 8, tn = tx * 8;
    float acc[8][8] = {};

    #pragma unroll 1
    for (int kt = 0; kt < 32; ++kt) {
        const int cur = kt & 1;
        if (kt < 31) {
            const float* Ap = Ag + (kt + 1) * 16;
            a0 = *(const float4*)(Ap + (size_t)ar0 * DDIM + ak);
            a1 = *(const float4*)(Ap + (size_t)ar1 * DDIM + ak);
            const float* Bp = W1 + (size_t)(kt + 1) * 16 * H1DIM;
            b0 = *(const float4*)(Bp + (size_t)bk0 * H1DIM + bn + bn4);
            b1 = *(const float4*)(Bp + (size_t)bk1 * H1DIM + bn + bn4);
        }
        #pragma unroll
        for (int kk = 0; kk < 16; ++kk) {
            float4 av0 = *(float4*)&As[cur][kk][tm];
            float4 av1 = *(float4*)&As[cur][kk][tm + 4];
            float4 bv0 = *(float4*)&Bs[cur][kk][tn];
            float4 bv1 = *(float4*)&Bs[cur][kk][tn + 4];
            float aa[8] = {av0.x, av0.y, av0.z, av0.w, av1.x, av1.y, av1.z, av1.w};
            float bb[8] = {bv0.x, bv0.y, bv0.z, bv0.w, bv1.x, bv1.y, bv1.z, bv1.w};
            #pragma unroll
            for (int ii = 0; ii < 8; ++ii)
                #pragma unroll
                for (int jj = 0; jj < 8; ++jj)
                    acc[ii][jj] = fmaf(aa[ii], bb[jj], acc[ii][jj]);
        }
        if (kt < 31) {
            const int nx = cur ^ 1;
            As[nx][ak+0][ar0] = a0.x; As[nx][ak+1][ar0] = a0.y; As[nx][ak+2][ar0] = a0.z; As[nx][ak+3][ar0] = a0.w;
            As[nx][ak+0][ar1] = a1.x; As[nx][ak+1][ar1] = a1.y; As[nx][ak+2][ar1] = a1.z; As[nx][ak+3][ar1] = a1.w;
            *(float4*)&Bs[nx][bk0][bn4] = b0;
            *(float4*)&Bs[nx][bk1][bn4] = b1;
            __syncthreads();
        }
    }

    float bv[8];
    #pragma unroll
    for (int j = 0; j < 8; ++j) bv[j] = bias1[bn + tn + j];
    float gs[8] = {};
    #pragma unroll
    for (int ii = 0; ii < 8; ++ii) {
        #pragma unroll
        for (int jj = 0; jj < 8; ++jj) {
            float hx = acc[ii][jj] + bv[jj];
            gs[jj] += (hx >= 0.0f ? hx : 0.01f * hx);
        }
    }
    const int grp = (bm >> 3) + ty;          // global group 0..8191
    float* orow = g_Hs + (size_t)grp * H1DIM + bn + tn;
    *(float4*)(orow)     = make_float4(gs[0], gs[1], gs[2], gs[3]);
    *(float4*)(orow + 4) = make_float4(gs[4], gs[5], gs[6], gs[7]);
}

// ---------------------------------------------------------------------------
// K2: P[n] = ((Hs[b*512+h] + Hs[b*512+h+1]) @ W2 + 16*b2) / 16
// M=8176 K=256 N=64 ; 128x64x16 tiles, 8x4/thread; A gathered as pair sums.
// ---------------------------------------------------------------------------
__global__ __launch_bounds__(256)
void k_p2(const float* __restrict__ W2, const float* __restrict__ bias2)
{
    __shared__ float As[2][16][132];
    __shared__ float Bs[2][16][64];
    const int bm = blockIdx.x * 128;
    const int tid = threadIdx.x;

    const int ar0 = tid >> 2;            // 0..63
    const int ar1 = ar0 + 64;
    const int ak  = (tid & 3) * 4;
    const int bk  = tid >> 4;            // 0..15
    const int bn4 = (tid & 15) * 4;

    int n0 = bm + ar0; if (n0 > NROWS - 1) n0 = NROWS - 1;
    int n1 = bm + ar1; if (n1 > NROWS - 1) n1 = NROWS - 1;
    const int b0i = n0 / NPAT, h0i = n0 - b0i * NPAT;
    const int b1i = n1 / NPAT, h1i = n1 - b1i * NPAT;
    const float* r0 = g_Hs + ((size_t)(b0i * 512 + h0i)) * H1DIM;
    const float* r1 = g_Hs + ((size_t)(b1i * 512 + h1i)) * H1DIM;

    float4 a0, a1, b0;
    {
        float4 p = *(const float4*)(r0 + ak);
        float4 q = *(const float4*)(r0 + H1DIM + ak);
        a0 = make_float4(p.x + q.x, p.y + q.y, p.z + q.z, p.w + q.w);
        p = *(const float4*)(r1 + ak);
        q = *(const float4*)(r1 + H1DIM + ak);
        a1 = make_float4(p.x + q.x, p.y + q.y, p.z + q.z, p.w + q.w);
    }
    b0 = *(const float4*)(W2 + (size_t)bk * EDIM + bn4);
    As[0][ak+0][ar0] = a0.x; As[0][ak+1][ar0] = a0.y; As[0][ak+2][ar0] = a0.z; As[0][ak+3][ar0] = a0.w;
    As[0][ak+0][ar1] = a1.x; As[0][ak+1][ar1] = a1.y; As[0][ak+2][ar1] = a1.z; As[0][ak+3][ar1] = a1.w;
    *(float4*)&Bs[0][bk][bn4] = b0;
    __syncthreads();

    const int tx = tid & 15, ty = tid >> 4;
    const int tm = ty * 8, tn = tx * 4;
    float acc[8][4] = {};

    #pragma unroll 1
    for (int kt = 0; kt < 16; ++kt) {
        const int cur = kt & 1;
        if (kt < 15) {
            const int ko = (kt + 1) * 16 + ak;
            float4 p = *(const float4*)(r0 + ko);
            float4 q = *(const float4*)(r0 + H1DIM + ko);
            a0 = make_float4(p.x + q.x, p.y + q.y, p.z + q.z, p.w + q.w);
            p = *(const float4*)(r1 + ko);
            q = *(const float4*)(r1 + H1DIM + ko);
            a1 = make_float4(p.x + q.x, p.y + q.y, p.z + q.z, p.w + q.w);
            b0 = *(const float4*)(W2 + (size_t)((kt + 1) * 16 + bk) * EDIM + bn4);
        }
        #pragma unroll
        for (int kk = 0; kk < 16; ++kk) {
            float4 av0 = *(float4*)&As[cur][kk][tm];
            float4 av1 = *(float4*)&As[cur][kk][tm + 4];
            float4 bv  = *(float4*)&Bs[cur][kk][tn];
            float aa[8] = {av0.x, av0.y, av0.z, av0.w, av1.x, av1.y, av1.z, av1.w};
            float bb[4] = {bv.x, bv.y, bv.z, bv.w};
            #pragma unroll
            for (int ii = 0; ii < 8; ++ii)
                #pragma unroll
                for (int jj = 0; jj < 4; ++jj)
                    acc[ii][jj] = fmaf(aa[ii], bb[jj], acc[ii][jj]);
        }
        if (kt < 15) {
            const int nx = cur ^ 1;
            As[nx][ak+0][ar0] = a0.x; As[nx][ak+1][ar0] = a0.y; As[nx][ak+2][ar0] = a0.z; As[nx][ak+3][ar0] = a0.w;
            As[nx][ak+0][ar1] = a1.x; As[nx][ak+1][ar1] = a1.y; As[nx][ak+2][ar1] = a1.z; As[nx][ak+3][ar1] = a1.w;
            *(float4*)&Bs[nx][bk][bn4] = b0;
            __syncthreads();
        }
    }

    float bv2[4];
    #pragma unroll
    for (int j = 0; j < 4; ++j) bv2[j] = bias2[tn + j];
    #pragma unroll
    for (int ii = 0; ii < 8; ++ii) {
        int n = bm + tm + ii;
        if (n < NROWS) {
            float4 o = make_float4(acc[ii][0] * 0.0625f + bv2[0],
                                   acc[ii][1] * 0.0625f + bv2[1],
                                   acc[ii][2] * 0.0625f + bv2[2],
                                   acc[ii][3] * 0.0625f + bv2[3]);
            *(float4*)(g_P + (size_t)n * EDIM + tn) = o;
        }
    }
}

// ---------------------------------------------------------------------------
// relu(tanh(m)) via odd deg-11 Taylor (|m|<=0.5), MUFU-free
// ---------------------------------------------------------------------------
__device__ __forceinline__ float arelu(float xi, float yi, float xj, float yj)
{
    float m  = fmaf(xi, yj, -(yi * xj));
    float m2 = m * m;
    float t;
    if (m2 > 0.25f) {
        t = tanhf(m);
    } else {
        float p = fmaf(m2, -8.863236e-3f, 2.1869488e-2f);
        p = fmaf(m2, p, -5.3968254e-2f);
        p = fmaf(m2, p,  1.3333334e-1f);
        p = fmaf(m2, p, -3.3333334e-1f);
        t = fmaf(m * m2, p, m);
    }
    return fmaxf(t, 0.0f);
}

// ---------------------------------------------------------------------------
// K4: attention + aggregation, single-pass packed top-8.  (58.8us measured)
// ---------------------------------------------------------------------------
__global__ __launch_bounds__(512)
void k_attn(const float* __restrict__ Wq, const float* __restrict__ Wk,
            const float* __restrict__ Wv, const float* __restrict__ Wa,
            const float* __restrict__ ba)
{
    __shared__ float sWq[4096];
    __shared__ float sWk[4096];
    __shared__ float sp[512];
    __shared__ float sqn[512];
    __shared__ float skn[512];
    __shared__ float sv[512];
    __shared__ float sav[512];
    __shared__ float sred[32];

    const int tid = threadIdx.x;
    #pragma unroll
    for (int idx = tid; idx < 4096; idx += 512) {
        sWq[idx] = Wq[idx];
        sWk[idx] = Wk[idx];
    }
    const int r = tid >> 6;
    const int i = tid & 63;
    const int n = blockIdx.x * 8 + r;
    sp[tid] = g_P[(size_t)n * EDIM + i];
    __syncthreads();

    float q = 0.f, k = 0.f, v = 0.f;
    const float* prow = sp + r * 64;
    #pragma unroll 8
    for (int j = 0; j < 64; ++j) {
        float pj = prow[j];
        q = fmaf(pj, sWq[j * 64 + i], q);
        k = fmaf(pj, sWk[j * 64 + i], k);
        v = fmaf(pj, __ldg(Wv + j * 64 + i), v);
    }
    float q2 = q * q, k2 = k * k;
    #pragma unroll
    for (int o = 16; o > 0; o >>= 1) {
        q2 += __shfl_xor_sync(0xffffffffu, q2, o);
        k2 += __shfl_xor_sync(0xffffffffu, k2, o);
    }
    if ((i & 31) == 0) {
        int w = i >> 5;
        sred[r * 4 + w]     = q2;
        sred[r * 4 + 2 + w] = k2;
    }
    __syncthreads();
    const float invq = 1.0f / (sqrtf(sred[r * 4 + 0] + sred[r * 4 + 1]) + 1e-8f);
    const float invk = 1.0f / (sqrtf(sred[r * 4 + 2] + sred[r * 4 + 3]) + 1e-8f);
    sqn[tid] = q * invq;
    skn[tid] = k * invk;
    sv[tid]  = v;
    __syncthreads();

    const float xi = sqn[tid];
    const float yi = skn[tid];
    const float* xr = sqn + r * 64;
    const float* yr = skn + r * 64;
    const float* vr = sv  + r * 64;

    float t0=-1e30f,t1=-1e30f,t2=-1e30f,t3=-1e30f,
          t4=-1e30f,t5=-1e30f,t6=-1e30f,t7=-1e30f;
    #pragma unroll 8
    for (int j = 0; j < 64; ++j) {
        float a = arelu(xi, yi, xr[j], yr[j]);
        float y = __uint_as_float((__float_as_uint(a) & 0xFFFFFFC0u) | (uint32_t)j);
        float u;
        u = fminf(y, t0); t0 = fmaxf(y, t0); y = u;
        u = fminf(y, t1); t1 = fmaxf(y, t1); y = u;
        u = fminf(y, t2); t2 = fmaxf(y, t2); y = u;
        u = fminf(y, t3); t3 = fmaxf(y, t3); y = u;
        u = fminf(y, t4); t4 = fmaxf(y, t4); y = u;
        u = fminf(y, t5); t5 = fmaxf(y, t5); y = u;
        u = fminf(y, t6); t6 = fmaxf(y, t6); y = u;
        t7 = fmaxf(y, t7);
    }

    float S  = ((t0 + t1) + (t2 + t3)) + ((t4 + t5) + (t6 + t7));
    float av = 0.f;
    av = fmaf(t0, vr[__float_as_uint(t0) & 63u], av);
    av = fmaf(t1, vr[__float_as_uint(t1) & 63u], av);
    av = fmaf(t2, vr[__float_as_uint(t2) & 63u], av);
    av = fmaf(t3, vr[__float_as_uint(t3) & 63u], av);
    av = fmaf(t4, vr[__float_as_uint(t4) & 63u], av);
    av = fmaf(t5, vr[__float_as_uint(t5) & 63u], av);
    av = fmaf(t6, vr[__float_as_uint(t6) & 63u], av);
    av = fmaf(t7, vr[__float_as_uint(t7) & 63u], av);
    av = av / fmaxf(S, 1e-8f);
    sav[tid] = av;
    __syncthreads();

    float z = ba[i];
    const float* arow = sav + r * 64;
    #pragma unroll 8
    for (int j = 0; j < 64; ++j)
        z = fmaf(arow[j], __ldg(Wa + j * 64 + i), z);
    z = z >= 0.0f ? z : 0.01f * z;
    g_Z[(size_t)n * EDIM + i] = z;
}

// ---------------------------------------------------------------------------
// K5: fused scatter-average + decoder GEMM, v2.
// 128(M) x 128(N) per 256-thread block, 8x8/thread, K=64 in one smem stage.
// 0.25 smem loads per FMA (was 0.5 -> L1=96% bound at 145us).
// smem: Azt 64x132 + Bz 64x128 = 65 KB dynamic.
// ---------------------------------------------------------------------------
#define DEC_AZT_STRIDE 132
#define DEC_SMEM ((64 * DEC_AZT_STRIDE + 64 * 128) * 4)

__global__ __launch_bounds__(256)
void k_dec(const float* __restrict__ Wd, const float* __restrict__ bd,
           float* __restrict__ out)
{
    extern __shared__ float sm[];
    float* Azt = sm;                      // [k][m] 64 x 132
    float* Bz  = sm + 64 * DEC_AZT_STRIDE; // [k][n] 64 x 128

    const int bn = blockIdx.x * 128;
    const int bm = blockIdx.y * 128;
    const int tid = threadIdx.x;

    // B tile: 64 x 128.  Each thread: 8 float4 (32 floats).
    {
        int k0 = tid >> 2;                // 0..63
        int c0 = (tid & 3) * 32;          // 0,32,64,96
        const float* src = Wd + (size_t)k0 * 512 + bn + c0;
        float* dst = Bz + k0 * 128 + c0;
        #pragma unroll
        for (int u = 0; u < 32; u += 4)
            *(float4*)(dst + u) = *(const float4*)(src + u);
    }
    // A tile with scatter-average, stored transposed [k][m].
    {
        int rr   = tid >> 1;              // 0..127
        int kq   = (tid & 1) * 32;        // 0 or 32
        int gr = bm + rr;
        int b  = gr >> 12;                // L = 4096
        int l  = gr & 4095;
        int hb = l >> 3;
        int h0 = hb - 1;
        float s0 = (h0 >= 0)   ? 1.0f : 0.0f;
        float s1 = (hb <= 510) ? 1.0f : 0.0f;
        float inv = 1.0f / (s0 + s1);
        const float* z0 = g_Z + ((size_t)b * NPAT + (h0 >= 0   ? h0 : 0)) * 64;
        const float* z1 = g_Z + ((size_t)b * NPAT + (hb <= 510 ? hb : 0)) * 64;
        #pragma unroll
        for (int u = 0; u < 32; u += 4) {
            float4 a0 = *(const float4*)(z0 + kq + u);
            float4 a1 = *(const float4*)(z1 + kq + u);
            Azt[(kq + u + 0) * DEC_AZT_STRIDE + rr] = fmaf(a0.x, s0, a1.x * s1) * inv;
            Azt[(kq + u + 1) * DEC_AZT_STRIDE + rr] = fmaf(a0.y, s0, a1.y * s1) * inv;
            Azt[(kq + u + 2) * DEC_AZT_STRIDE + rr] = fmaf(a0.z, s0, a1.z * s1) * inv;
            Azt[(kq + u + 3) * DEC_AZT_STRIDE + rr] = fmaf(a0.w, s0, a1.w * s1) * inv;
        }
    }
    __syncthreads();

    const int tx = tid & 15, ty = tid >> 4;
    const int tm = ty * 8, tn = tx * 8;
    float acc[8][8] = {};
    #pragma unroll 8
    for (int kk = 0; kk < 64; ++kk) {
        float4 av0 = *(float4*)(Azt + kk * DEC_AZT_STRIDE + tm);
        float4 av1 = *(float4*)(Azt + kk * DEC_AZT_STRIDE + tm + 4);
        float4 bv0 = *(float4*)(Bz + kk * 128 + tn);
        float4 bv1 = *(float4*)(Bz + kk * 128 + tn + 4);
        float aa[8] = {av0.x, av0.y, av0.z, av0.w, av1.x, av1.y, av1.z, av1.w};
        float bb[8] = {bv0.x, bv0.y, bv0.z, bv0.w, bv1.x, bv1.y, bv1.z, bv1.w};
        #pragma unroll
        for (int ii = 0; ii < 8; ++ii)
            #pragma unroll
            for (int jj = 0; jj < 8; ++jj)
                acc[ii][jj] = fmaf(aa[ii], bb[jj], acc[ii][jj]);
    }

    float4 bi0 = *(const float4*)(bd + bn + tn);
    float4 bi1 = *(const float4*)(bd + bn + tn + 4);
    float bb[8] = {bi0.x, bi0.y, bi0.z, bi0.w, bi1.x, bi1.y, bi1.z, bi1.w};
    #pragma unroll
    for (int ii = 0; ii < 8; ++ii) {
        float* orow = out + (size_t)(bm + tm + ii) * 512 + bn + tn;
        *(float4*)(orow)     = make_float4(acc[ii][0] + bb[0], acc[ii][1] + bb[1],
                                           acc[ii][2] + bb[2], acc[ii][3] + bb[3]);
        *(float4*)(orow + 4) = make_float4(acc[ii][4] + bb[4], acc[ii][5] + bb[5],
                                           acc[ii][6] + bb[6], acc[ii][7] + bb[7]);
    }
}

// ---------------------------------------------------------------------------
extern "C" void kernel_launch(void* const* d_in, const int* in_sizes, int n_in,
                              void* d_out, int out_size)
{
    const float* X  = (const float*)d_in[0];
    const float* W1 = (const float*)d_in[1];
    const float* b1 = (const float*)d_in[2];
    const float* W2 = (const float*)d_in[3];
    const float* b2 = (const float*)d_in[4];
    const float* Wq = (const float*)d_in[5];
    const float* Wk = (const float*)d_in[6];
    const float* Wv = (const float*)d_in[7];
    const float* Wa = (const float*)d_in[8];
    const float* ba = (const float*)d_in[9];
    const float* Wd = (const float*)d_in[10];
    const float* bd = (const float*)d_in[11];
    float* out = (float*)d_out;

    cudaFuncSetAttribute(k_dec, cudaFuncAttributeMaxDynamicSharedMemorySize,
                         DEC_SMEM);

    k_enc1<<<dim3(2, 512), 256>>>(X, W1, b1);
    k_p2<<<64, 256>>>(W2, b2);
    k_attn<<<1022, 512>>>(Wq, Wk, Wv, Wa, ba);
    k_dec<<<dim3(4, 512), 256, DEC_SMEM>>>(Wd, bd, out);
}

// round 17
// speedup vs baseline: 1.1122x; 1.0871x over previous
#include <cuda_runtime.h>
#include <cstdint>

// ---------------------------------------------------------------------------
// Shapes:  X:(16,4096,512)  W1:(512,256) b1:(256)  W2:(256,64) b2:(64)
//          Wq/Wk/Wv/Wa:(64,64) ba:(64)  Wd:(64,512) bd:(512)
// PATCH=16 STRIDE=8 TOPK=8 EPS=1e-8 ; h=511 ; N=B*h=8176 ; M=B*L=65536
//
// Fusions:
//  (1) P[b,h] = ((Hs[b,h] + Hs[b,h+1]) @ W2 + 16*b2)/16,
//      Hs = 8-row group sums of leaky(X@W1+b1) (enc1 epilogue).
//  (2) out rows are identical within each stride-group of 8 (l>>3 fixes the
//      covering patches), so the decoder GEMM runs on 8192 distinct rows and
//      broadcast-writes each result to 8 consecutive output rows.
// ---------------------------------------------------------------------------
#define MROWS 65536
#define DDIM  512
#define H1DIM 256
#define EDIM  64
#define NPAT  511
#define NROWS 8176
#define NGRP  8192      // 16 batches * 512 groups

__device__ float g_Hs[(size_t)NGRP * H1DIM];    //  8 MB  group-summed H1
__device__ float g_P [(size_t)NROWS * EDIM];    //  2 MB
__device__ float g_Z [(size_t)NROWS * EDIM];    //  2 MB

// ---------------------------------------------------------------------------
// K1: group-summed leaky(X @ W1 + b1).  M=65536 K=512 N=256 ; 128x128x16
// tiles, 8x8/thread; epilogue reduces each thread's 8 rows (one group).
// ---------------------------------------------------------------------------
__global__ __launch_bounds__(256)
void k_enc1(const float* __restrict__ X, const float* __restrict__ W1,
            const float* __restrict__ bias1)
{
    __shared__ float As[2][16][132];
    __shared__ float Bs[2][16][128];
    const int bm = blockIdx.y * 128;
    const int bn = blockIdx.x * 128;
    const int tid = threadIdx.x;

    const int ar0 = tid >> 2;            // 0..63
    const int ar1 = ar0 + 64;
    const int ak  = (tid & 3) * 4;
    const int bk0 = tid >> 5;            // 0..7
    const int bk1 = bk0 + 8;
    const int bn4 = (tid & 31) * 4;

    const float* Ag = X + (size_t)bm * DDIM;

    float4 a0, a1, b0, b1;
    a0 = *(const float4*)(Ag + (size_t)ar0 * DDIM + ak);
    a1 = *(const float4*)(Ag + (size_t)ar1 * DDIM + ak);
    b0 = *(const float4*)(W1 + (size_t)bk0 * H1DIM + bn + bn4);
    b1 = *(const float4*)(W1 + (size_t)bk1 * H1DIM + bn + bn4);
    As[0][ak+0][ar0] = a0.x; As[0][ak+1][ar0] = a0.y; As[0][ak+2][ar0] = a0.z; As[0][ak+3][ar0] = a0.w;
    As[0][ak+0][ar1] = a1.x; As[0][ak+1][ar1] = a1.y; As[0][ak+2][ar1] = a1.z; As[0][ak+3][ar1] = a1.w;
    *(float4*)&Bs[0][bk0][bn4] = b0;
    *(float4*)&Bs[0][bk1][bn4] = b1;
    __syncthreads();

    const int tx = tid & 15, ty = tid >> 4;
    const int tm = ty * 8, tn = tx * 8;
    float acc[8][8] = {};

    #pragma unroll 1
    for (int kt = 0; kt < 32; ++kt) {
        const int cur = kt & 1;
        if (kt < 31) {
            const float* Ap = Ag + (kt + 1) * 16;
            a0 = *(const float4*)(Ap + (size_t)ar0 * DDIM + ak);
            a1 = *(const float4*)(Ap + (size_t)ar1 * DDIM + ak);
            const float* Bp = W1 + (size_t)(kt + 1) * 16 * H1DIM;
            b0 = *(const float4*)(Bp + (size_t)bk0 * H1DIM + bn + bn4);
            b1 = *(const float4*)(Bp + (size_t)bk1 * H1DIM + bn + bn4);
        }
        #pragma unroll
        for (int kk = 0; kk < 16; ++kk) {
            float4 av0 = *(float4*)&As[cur][kk][tm];
            float4 av1 = *(float4*)&As[cur][kk][tm + 4];
            float4 bv0 = *(float4*)&Bs[cur][kk][tn];
            float4 bv1 = *(float4*)&Bs[cur][kk][tn + 4];
            float aa[8] = {av0.x, av0.y, av0.z, av0.w, av1.x, av1.y, av1.z, av1.w};
            float bb[8] = {bv0.x, bv0.y, bv0.z, bv0.w, bv1.x, bv1.y, bv1.z, bv1.w};
            #pragma unroll
            for (int ii = 0; ii < 8; ++ii)
                #pragma unroll
                for (int jj = 0; jj < 8; ++jj)
                    acc[ii][jj] = fmaf(aa[ii], bb[jj], acc[ii][jj]);
        }
        if (kt < 31) {
            const int nx = cur ^ 1;
            As[nx][ak+0][ar0] = a0.x; As[nx][ak+1][ar0] = a0.y; As[nx][ak+2][ar0] = a0.z; As[nx][ak+3][ar0] = a0.w;
            As[nx][ak+0][ar1] = a1.x; As[nx][ak+1][ar1] = a1.y; As[nx][ak+2][ar1] = a1.z; As[nx][ak+3][ar1] = a1.w;
            *(float4*)&Bs[nx][bk0][bn4] = b0;
            *(float4*)&Bs[nx][bk1][bn4] = b1;
            __syncthreads();
        }
    }

    float bv[8];
    #pragma unroll
    for (int j = 0; j < 8; ++j) bv[j] = bias1[bn + tn + j];
    float gs[8] = {};
    #pragma unroll
    for (int ii = 0; ii < 8; ++ii) {
        #pragma unroll
        for (int jj = 0; jj < 8; ++jj) {
            float hx = acc[ii][jj] + bv[jj];
            gs[jj] += (hx >= 0.0f ? hx : 0.01f * hx);
        }
    }
    const int grp = (bm >> 3) + ty;          // global group 0..8191
    float* orow = g_Hs + (size_t)grp * H1DIM + bn + tn;
    *(float4*)(orow)     = make_float4(gs[0], gs[1], gs[2], gs[3]);
    *(float4*)(orow + 4) = make_float4(gs[4], gs[5], gs[6], gs[7]);
}

// ---------------------------------------------------------------------------
// K2: P[n] = ((Hs[b*512+h] + Hs[b*512+h+1]) @ W2 + 16*b2) / 16
// M=8176 K=256 N=64 ; 128x64x16 tiles, 8x4/thread; A gathered as pair sums.
// ---------------------------------------------------------------------------
__global__ __launch_bounds__(256)
void k_p2(const float* __restrict__ W2, const float* __restrict__ bias2)
{
    __shared__ float As[2][16][132];
    __shared__ float Bs[2][16][64];
    const int bm = blockIdx.x * 128;
    const int tid = threadIdx.x;

    const int ar0 = tid >> 2;            // 0..63
    const int ar1 = ar0 + 64;
    const int ak  = (tid & 3) * 4;
    const int bk  = tid >> 4;            // 0..15
    const int bn4 = (tid & 15) * 4;

    int n0 = bm + ar0; if (n0 > NROWS - 1) n0 = NROWS - 1;
    int n1 = bm + ar1; if (n1 > NROWS - 1) n1 = NROWS - 1;
    const int b0i = n0 / NPAT, h0i = n0 - b0i * NPAT;
    const int b1i = n1 / NPAT, h1i = n1 - b1i * NPAT;
    const float* r0 = g_Hs + ((size_t)(b0i * 512 + h0i)) * H1DIM;
    const float* r1 = g_Hs + ((size_t)(b1i * 512 + h1i)) * H1DIM;

    float4 a0, a1, b0;
    {
        float4 p = *(const float4*)(r0 + ak);
        float4 q = *(const float4*)(r0 + H1DIM + ak);
        a0 = make_float4(p.x + q.x, p.y + q.y, p.z + q.z, p.w + q.w);
        p = *(const float4*)(r1 + ak);
        q = *(const float4*)(r1 + H1DIM + ak);
        a1 = make_float4(p.x + q.x, p.y + q.y, p.z + q.z, p.w + q.w);
    }
    b0 = *(const float4*)(W2 + (size_t)bk * EDIM + bn4);
    As[0][ak+0][ar0] = a0.x; As[0][ak+1][ar0] = a0.y; As[0][ak+2][ar0] = a0.z; As[0][ak+3][ar0] = a0.w;
    As[0][ak+0][ar1] = a1.x; As[0][ak+1][ar1] = a1.y; As[0][ak+2][ar1] = a1.z; As[0][ak+3][ar1] = a1.w;
    *(float4*)&Bs[0][bk][bn4] = b0;
    __syncthreads();

    const int tx = tid & 15, ty = tid >> 4;
    const int tm = ty * 8, tn = tx * 4;
    float acc[8][4] = {};

    #pragma unroll 1
    for (int kt = 0; kt < 16; ++kt) {
        const int cur = kt & 1;
        if (kt < 15) {
            const int ko = (kt + 1) * 16 + ak;
            float4 p = *(const float4*)(r0 + ko);
            float4 q = *(const float4*)(r0 + H1DIM + ko);
            a0 = make_float4(p.x + q.x, p.y + q.y, p.z + q.z, p.w + q.w);
            p = *(const float4*)(r1 + ko);
            q = *(const float4*)(r1 + H1DIM + ko);
            a1 = make_float4(p.x + q.x, p.y + q.y, p.z + q.z, p.w + q.w);
            b0 = *(const float4*)(W2 + (size_t)((kt + 1) * 16 + bk) * EDIM + bn4);
        }
        #pragma unroll
        for (int kk = 0; kk < 16; ++kk) {
            float4 av0 = *(float4*)&As[cur][kk][tm];
            float4 av1 = *(float4*)&As[cur][kk][tm + 4];
            float4 bv  = *(float4*)&Bs[cur][kk][tn];
            float aa[8] = {av0.x, av0.y, av0.z, av0.w, av1.x, av1.y, av1.z, av1.w};
            float bb[4] = {bv.x, bv.y, bv.z, bv.w};
            #pragma unroll
            for (int ii = 0; ii < 8; ++ii)
                #pragma unroll
                for (int jj = 0; jj < 4; ++jj)
                    acc[ii][jj] = fmaf(aa[ii], bb[jj], acc[ii][jj]);
        }
        if (kt < 15) {
            const int nx = cur ^ 1;
            As[nx][ak+0][ar0] = a0.x; As[nx][ak+1][ar0] = a0.y; As[nx][ak+2][ar0] = a0.z; As[nx][ak+3][ar0] = a0.w;
            As[nx][ak+0][ar1] = a1.x; As[nx][ak+1][ar1] = a1.y; As[nx][ak+2][ar1] = a1.z; As[nx][ak+3][ar1] = a1.w;
            *(float4*)&Bs[nx][bk][bn4] = b0;
            __syncthreads();
        }
    }

    float bv2[4];
    #pragma unroll
    for (int j = 0; j < 4; ++j) bv2[j] = bias2[tn + j];
    #pragma unroll
    for (int ii = 0; ii < 8; ++ii) {
        int n = bm + tm + ii;
        if (n < NROWS) {
            float4 o = make_float4(acc[ii][0] * 0.0625f + bv2[0],
                                   acc[ii][1] * 0.0625f + bv2[1],
                                   acc[ii][2] * 0.0625f + bv2[2],
                                   acc[ii][3] * 0.0625f + bv2[3]);
            *(float4*)(g_P + (size_t)n * EDIM + tn) = o;
        }
    }
}

// ---------------------------------------------------------------------------
// relu(tanh(m)) via odd deg-11 Taylor (|m|<=0.5), MUFU-free
// ---------------------------------------------------------------------------
__device__ __forceinline__ float arelu(float xi, float yi, float xj, float yj)
{
    float m  = fmaf(xi, yj, -(yi * xj));
    float m2 = m * m;
    float t;
    if (m2 > 0.25f) {
        t = tanhf(m);
    } else {
        float p = fmaf(m2, -8.863236e-3f, 2.1869488e-2f);
        p = fmaf(m2, p, -5.3968254e-2f);
        p = fmaf(m2, p,  1.3333334e-1f);
        p = fmaf(m2, p, -3.3333334e-1f);
        t = fmaf(m * m2, p, m);
    }
    return fmaxf(t, 0.0f);
}

// ---------------------------------------------------------------------------
// K4: attention + aggregation, single-pass packed top-8.  (58.8us measured)
// ---------------------------------------------------------------------------
__global__ __launch_bounds__(512)
void k_attn(const float* __restrict__ Wq, const float* __restrict__ Wk,
            const float* __restrict__ Wv, const float* __restrict__ Wa,
            const float* __restrict__ ba)
{
    __shared__ float sWq[4096];
    __shared__ float sWk[4096];
    __shared__ float sp[512];
    __shared__ float sqn[512];
    __shared__ float skn[512];
    __shared__ float sv[512];
    __shared__ float sav[512];
    __shared__ float sred[32];

    const int tid = threadIdx.x;
    #pragma unroll
    for (int idx = tid; idx < 4096; idx += 512) {
        sWq[idx] = Wq[idx];
        sWk[idx] = Wk[idx];
    }
    const int r = tid >> 6;
    const int i = tid & 63;
    const int n = blockIdx.x * 8 + r;
    sp[tid] = g_P[(size_t)n * EDIM + i];
    __syncthreads();

    float q = 0.f, k = 0.f, v = 0.f;
    const float* prow = sp + r * 64;
    #pragma unroll 8
    for (int j = 0; j < 64; ++j) {
        float pj = prow[j];
        q = fmaf(pj, sWq[j * 64 + i], q);
        k = fmaf(pj, sWk[j * 64 + i], k);
        v = fmaf(pj, __ldg(Wv + j * 64 + i), v);
    }
    float q2 = q * q, k2 = k * k;
    #pragma unroll
    for (int o = 16; o > 0; o >>= 1) {
        q2 += __shfl_xor_sync(0xffffffffu, q2, o);
        k2 += __shfl_xor_sync(0xffffffffu, k2, o);
    }
    if ((i & 31) == 0) {
        int w = i >> 5;
        sred[r * 4 + w]     = q2;
        sred[r * 4 + 2 + w] = k2;
    }
    __syncthreads();
    const float invq = 1.0f / (sqrtf(sred[r * 4 + 0] + sred[r * 4 + 1]) + 1e-8f);
    const float invk = 1.0f / (sqrtf(sred[r * 4 + 2] + sred[r * 4 + 3]) + 1e-8f);
    sqn[tid] = q * invq;
    skn[tid] = k * invk;
    sv[tid]  = v;
    __syncthreads();

    const float xi = sqn[tid];
    const float yi = skn[tid];
    const float* xr = sqn + r * 64;
    const float* yr = skn + r * 64;
    const float* vr = sv  + r * 64;

    float t0=-1e30f,t1=-1e30f,t2=-1e30f,t3=-1e30f,
          t4=-1e30f,t5=-1e30f,t6=-1e30f,t7=-1e30f;
    #pragma unroll 8
    for (int j = 0; j < 64; ++j) {
        float a = arelu(xi, yi, xr[j], yr[j]);
        float y = __uint_as_float((__float_as_uint(a) & 0xFFFFFFC0u) | (uint32_t)j);
        float u;
        u = fminf(y, t0); t0 = fmaxf(y, t0); y = u;
        u = fminf(y, t1); t1 = fmaxf(y, t1); y = u;
        u = fminf(y, t2); t2 = fmaxf(y, t2); y = u;
        u = fminf(y, t3); t3 = fmaxf(y, t3); y = u;
        u = fminf(y, t4); t4 = fmaxf(y, t4); y = u;
        u = fminf(y, t5); t5 = fmaxf(y, t5); y = u;
        u = fminf(y, t6); t6 = fmaxf(y, t6); y = u;
        t7 = fmaxf(y, t7);
    }

    float S  = ((t0 + t1) + (t2 + t3)) + ((t4 + t5) + (t6 + t7));
    float av = 0.f;
    av = fmaf(t0, vr[__float_as_uint(t0) & 63u], av);
    av = fmaf(t1, vr[__float_as_uint(t1) & 63u], av);
    av = fmaf(t2, vr[__float_as_uint(t2) & 63u], av);
    av = fmaf(t3, vr[__float_as_uint(t3) & 63u], av);
    av = fmaf(t4, vr[__float_as_uint(t4) & 63u], av);
    av = fmaf(t5, vr[__float_as_uint(t5) & 63u], av);
    av = fmaf(t6, vr[__float_as_uint(t6) & 63u], av);
    av = fmaf(t7, vr[__float_as_uint(t7) & 63u], av);
    av = av / fmaxf(S, 1e-8f);
    sav[tid] = av;
    __syncthreads();

    float z = ba[i];
    const float* arow = sav + r * 64;
    #pragma unroll 8
    for (int j = 0; j < 64; ++j)
        z = fmaf(arow[j], __ldg(Wa + j * 64 + i), z);
    z = z >= 0.0f ? z : 0.01f * z;
    g_Z[(size_t)n * EDIM + i] = z;
}

// ---------------------------------------------------------------------------
// K5 v3: decoder on DISTINCT rows only + 8x broadcast write.
// W[gi] = avg(Z[b,g-1],Z[b,g]) @ Wd + bd for gi = b*512+g (8192 rows);
// out rows 8*gi .. 8*gi+7 all equal W[gi].
// Block: 64 groups x 128 cols, 256 threads, 4x8/thread, K=64 single stage.
// smem: Azt 64x68 + Bz 64x128 = 50 KB dynamic -> 4 CTAs/SM.
// ---------------------------------------------------------------------------
#define DC_AS 68
#define DC_SMEM ((64 * DC_AS + 64 * 128) * 4)

__global__ __launch_bounds__(256)
void k_dec(const float* __restrict__ Wd, const float* __restrict__ bd,
           float* __restrict__ out)
{
    extern __shared__ float sm[];
    float* Azt = sm;                 // [k][m] 64 x 68
    float* Bz  = sm + 64 * DC_AS;    // [k][n] 64 x 128

    const int bn = blockIdx.x * 128;
    const int bg = blockIdx.y * 64;
    const int tid = threadIdx.x;

    // B tile: 64 x 128 (each thread 8 float4)
    {
        int k0 = tid >> 2;               // 0..63
        int c0 = (tid & 3) * 32;         // 0,32,64,96
        const float* src = Wd + (size_t)k0 * 512 + bn + c0;
        float* dst = Bz + k0 * 128 + c0;
        #pragma unroll
        for (int u = 0; u < 32; u += 4)
            *(float4*)(dst + u) = *(const float4*)(src + u);
    }
    // A tile: distinct-group averages, stored transposed [k][m]
    {
        int rr = tid >> 2;               // group within tile 0..63
        int kq = (tid & 3) * 16;         // 16 k-values
        int gi = bg + rr;
        int b  = gi >> 9;                // 512 groups per batch
        int g  = gi & 511;
        float s0 = (g >= 1)   ? 1.0f : 0.0f;
        float s1 = (g <= 510) ? 1.0f : 0.0f;
        float inv = 1.0f / (s0 + s1);
        const float* z0 = g_Z + ((size_t)b * NPAT + (g >= 1   ? g - 1 : 0)) * 64;
        const float* z1 = g_Z + ((size_t)b * NPAT + (g <= 510 ? g     : 0)) * 64;
        #pragma unroll
        for (int u = 0; u < 16; u += 4) {
            float4 a0 = *(const float4*)(z0 + kq + u);
            float4 a1 = *(const float4*)(z1 + kq + u);
            Azt[(kq + u + 0) * DC_AS + rr] = fmaf(a0.x, s0, a1.x * s1) * inv;
            Azt[(kq + u + 1) * DC_AS + rr] = fmaf(a0.y, s0, a1.y * s1) * inv;
            Azt[(kq + u + 2) * DC_AS + rr] = fmaf(a0.z, s0, a1.z * s1) * inv;
            Azt[(kq + u + 3) * DC_AS + rr] = fmaf(a0.w, s0, a1.w * s1) * inv;
        }
    }
    __syncthreads();

    const int tx = tid & 15, ty = tid >> 4;
    const int tm = ty * 4, tn = tx * 8;
    float acc[4][8] = {};
    #pragma unroll 8
    for (int kk = 0; kk < 64; ++kk) {
        float4 av  = *(float4*)(Azt + kk * DC_AS + tm);
        float4 bv0 = *(float4*)(Bz + kk * 128 + tn);
        float4 bv1 = *(float4*)(Bz + kk * 128 + tn + 4);
        float aa[4] = {av.x, av.y, av.z, av.w};
        float bb[8] = {bv0.x, bv0.y, bv0.z, bv0.w, bv1.x, bv1.y, bv1.z, bv1.w};
        #pragma unroll
        for (int ii = 0; ii < 4; ++ii)
            #pragma unroll
            for (int jj = 0; jj < 8; ++jj)
                acc[ii][jj] = fmaf(aa[ii], bb[jj], acc[ii][jj]);
    }

    float4 bi0 = *(const float4*)(bd + bn + tn);
    float4 bi1 = *(const float4*)(bd + bn + tn + 4);
    #pragma unroll
    for (int ii = 0; ii < 4; ++ii) {
        float4 o0 = make_float4(acc[ii][0] + bi0.x, acc[ii][1] + bi0.y,
                                acc[ii][2] + bi0.z, acc[ii][3] + bi0.w);
        float4 o1 = make_float4(acc[ii][4] + bi1.x, acc[ii][5] + bi1.y,
                                acc[ii][6] + bi1.z, acc[ii][7] + bi1.w);
        // broadcast to the 8 identical output rows (contiguous: 8*gi + p)
        float* orow = out + (size_t)(bg + tm + ii) * 8 * 512 + bn + tn;
        #pragma unroll
        for (int p = 0; p < 8; ++p) {
            *(float4*)(orow)     = o0;
            *(float4*)(orow + 4) = o1;
            orow += 512;
        }
    }
}

// ---------------------------------------------------------------------------
extern "C" void kernel_launch(void* const* d_in, const int* in_sizes, int n_in,
                              void* d_out, int out_size)
{
    const float* X  = (const float*)d_in[0];
    const float* W1 = (const float*)d_in[1];
    const float* b1 = (const float*)d_in[2];
    const float* W2 = (const float*)d_in[3];
    const float* b2 = (const float*)d_in[4];
    const float* Wq = (const float*)d_in[5];
    const float* Wk = (const float*)d_in[6];
    const float* Wv = (const float*)d_in[7];
    const float* Wa = (const float*)d_in[8];
    const float* ba = (const float*)d_in[9];
    const float* Wd = (const float*)d_in[10];
    const float* bd = (const float*)d_in[11];
    float* out = (float*)d_out;

    cudaFuncSetAttribute(k_dec, cudaFuncAttributeMaxDynamicSharedMemorySize,
                         DC_SMEM);

    k_enc1<<<dim3(2, 512), 256>>>(X, W1, b1);
    k_p2<<<64, 256>>>(W2, b2);
    k_attn<<<1022, 512>>>(Wq, Wk, Wv, Wa, ba);
    k_dec<<<dim3(4, 128), 256, DC_SMEM>>>(Wd, bd, out);
}